// round 6
// baseline (speedup 1.0000x reference)
#include <cuda_runtime.h>
#include <cuda_fp16.h>
#include <math.h>
#include <stdint.h>

// ---------------- problem dims ----------------
#define Bsz 4096
#define Hd  2048
#define Kd  2048
#define AP  (4096ull*2048ull)
#define WP  (2048ull*2048ull)

// ---------------- device scratch ----------------
__device__ float g_Z [(size_t)Bsz*(5*Hd)];  // [B,5H]: i|f|g|o_part|resid
__device__ float g_Z2[(size_t)Bsz*(2*Hd)];  // [B,2H]: c@w_co | tanh(c)@w_c
// fp16 activations [plane][B][K]; plane: 0=x 1=h 2=c_prev 3=c_new 4=tanh(c_new)
__device__ __half g_Act[5ull*AP];
// s8 activations, same planes: round(v*16), clamped
__device__ signed char g_Act8[5ull*AP];
// fp16 weight hi [widx][N][K] (transposed)
// widx: 0 wxi 1 whi 2 wci 3 wxf 4 whf 5 wcf 6 wxg 7 whg 8 wxo 9 who 10 wco 11 wc 12 wi
__device__ __half g_Wt[13ull*WP];
// s8 weight lo: round((w - fp16(w)) * 2^21), clamped
__device__ signed char g_Wlo8[13ull*WP];

#define LO_SCALE 2.9802322387695312e-8f   // 2^-25 = 1/(16 * 2^21)

// ---------------- unit tables ----------------
// groups: 0=i 1=f 2=g 3=o 4=resid 5=co 6=c ; each unit = (activation, weight)
__constant__ int c_nunit[7] = {3, 3, 2, 2, 1, 1, 1};
__constant__ unsigned char c_unit_a[7][3] = {
    {0,1,2}, {0,1,2}, {0,1,0}, {0,1,0}, {0,0,0}, {3,0,0}, {4,0,0}
};
__constant__ unsigned char c_unit_w[7][3] = {
    {0,1,2}, {3,4,5}, {6,7,0}, {8,9,0}, {12,0,0}, {10,0,0}, {11,0,0}
};

// ---------------- GEMM tiling ----------------
#define BM 128
#define BN 128
#define BKc 32
#define KPAD 40                     // fp16 row pitch (elems): 80 B
#define S8PITCH 48                  // s8 row pitch (bytes): conflict-free
#define THREADS 256
// stage layout (bytes): A_f16 @0 (10240) | W_hi @10240 (10240) | A_s8 @20480 (6144) | W_lo8 @26624 (6144)
#define OFF_WH  10240
#define OFF_A8  20480
#define OFF_W8  26624
#define STAGE_B 32768
#define STAGES 3
#define SMEM_BYTES (STAGES*STAGE_B)   // 98304 -> 2 CTAs/SM

__device__ __forceinline__ uint32_t smem_u32(const void* p) {
    uint32_t a;
    asm("{ .reg .u64 t; cvta.to.shared.u64 t, %1; cvt.u32.u64 %0, t; }" : "=r"(a) : "l"(p));
    return a;
}
__device__ __forceinline__ void cp_async16(uint32_t sdst, const void* gsrc) {
    asm volatile("cp.async.cg.shared.global [%0], [%1], 16;"
                 :: "r"(sdst), "l"(__cvta_generic_to_global(gsrc)) : "memory");
}
#define CP_COMMIT() asm volatile("cp.async.commit_group;" ::: "memory")
#define CP_WAIT1()  asm volatile("cp.async.wait_group 1;" ::: "memory")

__device__ __forceinline__ void ldsm_x4(uint32_t& r0, uint32_t& r1, uint32_t& r2, uint32_t& r3,
                                        uint32_t addr) {
    asm volatile("ldmatrix.sync.aligned.m8n8.x4.shared.b16 {%0,%1,%2,%3}, [%4];"
                 : "=r"(r0), "=r"(r1), "=r"(r2), "=r"(r3) : "r"(addr));
}
__device__ __forceinline__ uint32_t lds32(uint32_t addr) {
    uint32_t v;
    asm volatile("ld.shared.b32 %0, [%1];" : "=r"(v) : "r"(addr));
    return v;
}
__device__ __forceinline__ void mma16816(float* d, const uint32_t* a, uint32_t b0, uint32_t b1) {
    asm volatile(
        "mma.sync.aligned.m16n8k16.row.col.f32.f16.f16.f32 "
        "{%0,%1,%2,%3}, {%4,%5,%6,%7}, {%8,%9}, {%0,%1,%2,%3};"
        : "+f"(d[0]), "+f"(d[1]), "+f"(d[2]), "+f"(d[3])
        : "r"(a[0]), "r"(a[1]), "r"(a[2]), "r"(a[3]), "r"(b0), "r"(b1));
}
__device__ __forceinline__ void mma_s8(int* d, const uint32_t* a, uint32_t b0, uint32_t b1) {
    const uint32_t z = 0;
    asm volatile(
        "mma.sync.aligned.m16n8k32.row.col.s32.s8.s8.s32 "
        "{%0,%1,%2,%3}, {%4,%5,%6,%7}, {%8,%9}, {%10,%11,%12,%13};"
        : "=r"(d[0]), "=r"(d[1]), "=r"(d[2]), "=r"(d[3])
        : "r"(a[0]), "r"(a[1]), "r"(a[2]), "r"(a[3]), "r"(b0), "r"(b1),
          "r"(z), "r"(z), "r"(z), "r"(z));
}

// ---------------- hybrid GEMM: fp16 hi pass + int8 lo pass ----------------
__global__ void __launch_bounds__(THREADS, 2) gemm_mma(
    int group_base,
    const float* __restrict__ bi, const float* __restrict__ bf_,
    const float* __restrict__ bg, const float* __restrict__ bo)
{
    extern __shared__ char smem[];
    const uint32_t sb = smem_u32(smem);

    const int tid  = threadIdx.x;
    const int lane = tid & 31;
    const int wid  = tid >> 5;      // 0..7
    const int wm   = wid >> 2;      // 0..1  (64-row slice)
    const int wn   = wid & 3;       // 0..3  (32-col slice)

    const int group = group_base + ((int)blockIdx.y >> 4);
    const int n0    = ((int)blockIdx.y & 15) * BN;
    const int m0    = (int)blockIdx.x * BM;

    const int nunit = c_nunit[group];
    const int nch   = nunit * (Kd / BKc);

    // fp16 ldmatrix per-lane byte offsets
    const uint32_t a_off = ((uint32_t)(wm*64 + (lane & 15)) * KPAD + ((lane >> 4) << 3)) * 2;
    const uint32_t w_off = ((uint32_t)(wn*32 + (lane & 7) + ((lane >> 4) << 3)) * KPAD
                            + (((lane >> 3) & 1) << 3)) * 2;
    // s8 per-lane offsets
    const int gidr = lane >> 2;           // 0..7
    const int kw4  = (lane & 3) * 4;      // 0,4,8,12
    const uint32_t a8_base = (uint32_t)(wm*64 + gidr) * S8PITCH + kw4;     // + mi*16*S8PITCH
    const uint32_t w8_base = (uint32_t)(wn*32 + gidr) * S8PITCH + kw4;     // + nt*8*S8PITCH

    float acc[4][4][4];
    #pragma unroll
    for (int mi = 0; mi < 4; ++mi)
        #pragma unroll
        for (int nj = 0; nj < 4; ++nj)
            #pragma unroll
            for (int r = 0; r < 4; ++r) acc[mi][nj][r] = 0.0f;

    // stage fill: 1792 x 16B chunks, 7 per thread
    // [0,640): A_f16 ; [640,1280): W_hi ; [1280,1536): A_s8 ; [1536,1792): W_lo8
    #define ISSUE(tt, buf) do {                                                         \
        const int _t = (tt);                                                            \
        const int _u  = _t >> 6;                                                        \
        const int _kk = (_t & 63) * BKc;                                                \
        const int _az = c_unit_a[group][_u];                                            \
        const int _wz = c_unit_w[group][_u];                                            \
        const __half* _gA = g_Act + (size_t)_az*AP;                                     \
        const __half* _gW = g_Wt  + (size_t)_wz*WP;                                     \
        const signed char* _gA8 = g_Act8 + (size_t)_az*AP;                              \
        const signed char* _gW8 = g_Wlo8 + (size_t)_wz*WP;                              \
        const uint32_t _sbase = sb + (uint32_t)(buf)*STAGE_B;                           \
        _Pragma("unroll")                                                               \
        for (int _i = 0; _i < 7; ++_i) {                                                \
            const int _cid = tid + _i*THREADS;                                          \
            if (_cid < 640) {                                                           \
                const int _r = _cid / 5, _w = _cid % 5;                                 \
                cp_async16(_sbase + (uint32_t)(_r*80 + _w*16),                          \
                           _gA + (size_t)(m0 + _r)*Kd + _kk + _w*8);                    \
            } else if (_cid < 1280) {                                                   \
                const int _b = _cid - 640;                                              \
                const int _r = _b / 5, _w = _b % 5;                                     \
                cp_async16(_sbase + OFF_WH + (uint32_t)(_r*80 + _w*16),                 \
                           _gW + (size_t)(n0 + _r)*Kd + _kk + _w*8);                    \
            } else if (_cid < 1536) {                                                   \
                const int _b = _cid - 1280;                                             \
                const int _r = _b >> 1, _w = _b & 1;                                    \
                cp_async16(_sbase + OFF_A8 + (uint32_t)(_r*S8PITCH + _w*16),            \
                           _gA8 + (size_t)(m0 + _r)*Kd + _kk + _w*16);                  \
            } else {                                                                    \
                const int _b = _cid - 1536;                                             \
                const int _r = _b >> 1, _w = _b & 1;                                    \
                cp_async16(_sbase + OFF_W8 + (uint32_t)(_r*S8PITCH + _w*16),            \
                           _gW8 + (size_t)(n0 + _r)*Kd + _kk + _w*16);                  \
            }                                                                           \
        }                                                                               \
    } while (0)

    ISSUE(0, 0); CP_COMMIT();
    ISSUE(1, 1); CP_COMMIT();

    int buf = 0;
    for (int t = 0; t < nch; ++t) {
        CP_WAIT1();
        __syncthreads();

        if (t + 2 < nch) {
            int nb = buf + 2; if (nb >= 3) nb -= 3;
            ISSUE(t + 2, nb);
        }
        CP_COMMIT();

        const uint32_t st = sb + (uint32_t)buf*STAGE_B;

        // ---- hi pass: fp16, 2 x k16 ----
        #pragma unroll
        for (int ks = 0; ks < 2; ++ks) {
            const uint32_t kso = (uint32_t)(ks*32);     // 16 halfs = 32 B
            uint32_t a[4][4], bh[2][4];
            #pragma unroll
            for (int mi = 0; mi < 4; ++mi)
                ldsm_x4(a[mi][0], a[mi][1], a[mi][2], a[mi][3],
                        st + a_off + (uint32_t)(mi*16*KPAD)*2 + kso);
            #pragma unroll
            for (int nt = 0; nt < 2; ++nt)
                ldsm_x4(bh[nt][0], bh[nt][1], bh[nt][2], bh[nt][3],
                        st + OFF_WH + w_off + (uint32_t)(nt*16*KPAD)*2 + kso);
            #pragma unroll
            for (int mi = 0; mi < 4; ++mi)
                #pragma unroll
                for (int nj = 0; nj < 4; ++nj)
                    mma16816(acc[mi][nj], a[mi],
                             bh[nj >> 1][(nj & 1)*2], bh[nj >> 1][(nj & 1)*2 + 1]);
        }

        // ---- lo pass: int8, 1 x k32 ----
        {
            uint32_t bs[4][2];
            #pragma unroll
            for (int nt = 0; nt < 4; ++nt) {
                const uint32_t wa = st + OFF_W8 + w8_base + (uint32_t)(nt*8*S8PITCH);
                bs[nt][0] = lds32(wa);
                bs[nt][1] = lds32(wa + 16);
            }
            #pragma unroll
            for (int mi = 0; mi < 4; ++mi) {
                uint32_t a8[4];
                const uint32_t aa = st + OFF_A8 + a8_base + (uint32_t)(mi*16*S8PITCH);
                a8[0] = lds32(aa);
                a8[1] = lds32(aa + 8*S8PITCH);
                a8[2] = lds32(aa + 16);
                a8[3] = lds32(aa + 8*S8PITCH + 16);
                #pragma unroll
                for (int nj = 0; nj < 4; ++nj) {
                    int d[4];
                    mma_s8(d, a8, bs[nj][0], bs[nj][1]);
                    #pragma unroll
                    for (int r = 0; r < 4; ++r)
                        acc[mi][nj][r] += (float)d[r] * LO_SCALE;
                }
            }
        }
        if (++buf == 3) buf = 0;
    }

    // ---- epilogue ----
    float* zout; size_t ldz; int colbase;
    const float* bias = nullptr;
    if (group < 5) {
        zout = g_Z;  ldz = 5*Hd; colbase = group*Hd + n0;
        if      (group == 0) bias = bi;
        else if (group == 1) bias = bf_;
        else if (group == 2) bias = bg;
        else if (group == 3) bias = bo;
    } else {
        zout = g_Z2; ldz = 2*Hd; colbase = (group - 5)*Hd + n0;
    }

    const int gid = lane >> 2;
    const int tig = lane & 3;

    #pragma unroll
    for (int mi = 0; mi < 4; ++mi) {
        const int row = m0 + wm*64 + mi*16 + gid;
        #pragma unroll
        for (int nj = 0; nj < 4; ++nj) {
            const int ncol = wn*32 + nj*8 + tig*2;
            float b0 = 0.f, b1 = 0.f;
            if (bias) { b0 = bias[n0 + ncol]; b1 = bias[n0 + ncol + 1]; }
            float2 v0 = make_float2(acc[mi][nj][0] + b0, acc[mi][nj][1] + b1);
            float2 v1 = make_float2(acc[mi][nj][2] + b0, acc[mi][nj][3] + b1);
            *(float2*)(zout + (size_t)row       * ldz + colbase + ncol) = v0;
            *(float2*)(zout + (size_t)(row + 8) * ldz + colbase + ncol) = v1;
        }
    }
}

// ---------------- conversion helpers ----------------
__device__ __forceinline__ signed char q8(float v, float s) {
    int q = __float2int_rn(v * s);
    q = max(-127, min(127, q));
    return (signed char)q;
}

// x/h/c fp32 -> fp16 + s8 planes 0..2
__global__ void __launch_bounds__(256) conv_act3(
    const float* __restrict__ x, const float* __restrict__ h, const float* __restrict__ c)
{
    const int act = blockIdx.y;
    const float* s = (act == 0) ? x : (act == 1) ? h : c;
    const size_t i = ((size_t)blockIdx.x*256 + threadIdx.x) * 4;
    float4 v = *(const float4*)(s + i);
    __half* dst = g_Act + (size_t)act*AP;
    signed char* d8 = g_Act8 + (size_t)act*AP;
    dst[i+0] = __float2half_rn(v.x);
    dst[i+1] = __float2half_rn(v.y);
    dst[i+2] = __float2half_rn(v.z);
    dst[i+3] = __float2half_rn(v.w);
    d8[i+0] = q8(v.x, 16.f);
    d8[i+1] = q8(v.y, 16.f);
    d8[i+2] = q8(v.z, 16.f);
    d8[i+3] = q8(v.w, 16.f);
}

struct WPtrs { const float* p[13]; };

// W[K][N] fp32 -> g_Wt[N][K] fp16 hi + g_Wlo8[N][K] s8 lo (transpose via smem)
__global__ void __launch_bounds__(256) conv_w(WPtrs wp)
{
    __shared__ float t[32][33];
    const int widx = blockIdx.z;
    const float* w = wp.p[widx];
    const int tx = threadIdx.x & 31;
    const int ty = threadIdx.x >> 5;
    const int k0 = blockIdx.x * 32;
    const int n0 = blockIdx.y * 32;
    #pragma unroll
    for (int r = 0; r < 4; ++r)
        t[ty + 8*r][tx] = w[(size_t)(k0 + ty + 8*r)*Hd + n0 + tx];
    __syncthreads();
    __half* hi = g_Wt + (size_t)widx*WP;
    signed char* lo = g_Wlo8 + (size_t)widx*WP;
    #pragma unroll
    for (int r = 0; r < 4; ++r) {
        const float v = t[tx][ty + 8*r];
        const size_t o = (size_t)(n0 + ty + 8*r)*Kd + k0 + tx;
        __half hb = __float2half_rn(v);
        hi[o] = hb;
        lo[o] = q8(v - __half2float(hb), 2097152.f);   // 2^21
    }
}

// ---------------- elementwise kernels ----------------
__global__ void __launch_bounds__(256) cell_kernel(
    const float* __restrict__ c_prev, float* __restrict__ c_out)
{
    const int idx = blockIdx.x * 256 + threadIdx.x;
    const int m = idx >> 11;
    const int j = idx & (Hd - 1);
    const float* zr = g_Z + (size_t)m * (5*Hd);
    const float iv = zr[j];
    const float fv = zr[Hd + j];
    const float gv = zr[2*Hd + j];
    const float cp = c_prev[idx];
    const float si = 1.0f / (1.0f + expf(-iv));
    const float sf = 1.0f / (1.0f + expf(-fv));
    const float cn = sf * cp + si * tanhf(gv);
    c_out[idx] = cn;
    const float tc = tanhf(cn);
    g_Act [3*AP + idx] = __float2half_rn(cn);
    g_Act [4*AP + idx] = __float2half_rn(tc);
    g_Act8[3*AP + idx] = q8(cn, 16.f);
    g_Act8[4*AP + idx] = q8(tc, 16.f);
}

__global__ void __launch_bounds__(256) out_kernel(float* __restrict__ h_out)
{
    const int idx = blockIdx.x * 256 + threadIdx.x;
    const int m = idx >> 11;
    const int j = idx & (Hd - 1);
    const float* zr  = g_Z  + (size_t)m * (5*Hd);
    const float* z2r = g_Z2 + (size_t)m * (2*Hd);
    const float o = zr[3*Hd + j] + z2r[j];
    const float t = z2r[Hd + j] + zr[4*Hd + j];
    h_out[idx] = tanhf(o) * t;
}

// ---------------- host launcher ----------------
extern "C" void kernel_launch(void* const* d_in, const int* in_sizes, int n_in,
                              void* d_out, int out_size)
{
    const float* x      = (const float*)d_in[0];
    const float* h_prev = (const float*)d_in[1];
    const float* c_prev = (const float*)d_in[2];
    const float* w_xi = (const float*)d_in[3];
    const float* w_hi = (const float*)d_in[4];
    const float* w_ci = (const float*)d_in[5];
    const float* w_xf = (const float*)d_in[6];
    const float* w_hf = (const float*)d_in[7];
    const float* w_cf = (const float*)d_in[8];
    const float* w_xg = (const float*)d_in[9];
    const float* w_hg = (const float*)d_in[10];
    const float* w_xo = (const float*)d_in[11];
    const float* w_ho = (const float*)d_in[12];
    const float* w_co = (const float*)d_in[13];
    const float* w_c  = (const float*)d_in[14];
    const float* w_i  = (const float*)d_in[15];
    const float* b_i  = (const float*)d_in[16];
    const float* b_f  = (const float*)d_in[17];
    const float* b_g  = (const float*)d_in[18];
    const float* b_o  = (const float*)d_in[19];

    float* out   = (float*)d_out;
    float* h_out = out;
    float* c_out = out + (size_t)Bsz * Hd;

    cudaFuncSetAttribute(gemm_mma, cudaFuncAttributeMaxDynamicSharedMemorySize, SMEM_BYTES);

    const int n = Bsz * Hd;

    conv_act3<<<dim3(n/(256*4), 3), 256>>>(x, h_prev, c_prev);

    WPtrs wp = {{w_xi, w_hi, w_ci, w_xf, w_hf, w_cf, w_xg, w_hg, w_xo, w_ho, w_co, w_c, w_i}};
    conv_w<<<dim3(Kd/32, Hd/32, 13), 256>>>(wp);

    gemm_mma<<<dim3(Bsz/BM, 5*16), THREADS, SMEM_BYTES>>>(0, b_i, b_f, b_g, b_o);

    cell_kernel<<<n/256, 256>>>(c_prev, c_out);

    gemm_mma<<<dim3(Bsz/BM, 2*16), THREADS, SMEM_BYTES>>>(5, nullptr, nullptr, nullptr, nullptr);

    out_kernel<<<n/256, 256>>>(h_out);
}

// round 8
// speedup vs baseline: 3.1638x; 3.1638x over previous
#include <cuda_runtime.h>
#include <cuda_fp16.h>
#include <math.h>
#include <stdint.h>

// ---------------- problem dims ----------------
#define Bsz 4096
#define Hd  2048
#define Kd  2048
#define AP  (4096ull*2048ull)   // activation plane elems
#define WP  (2048ull*2048ull)   // weight plane elems

// ---------------- device scratch ----------------
__device__ float g_Z [(size_t)Bsz*(5*Hd)];  // [B,5H]: i|f|g|o_part|resid
__device__ float g_Z2[(size_t)Bsz*(2*Hd)];  // [B,2H]: c@w_co | tanh(c)@w_c
// fp16 activations [plane][B][K]; plane: 0=x 1=h 2=c_prev 3=c_new 4=tanh(c_new)
__device__ __half g_Act[5ull*AP];
// fp16 weights transposed [widx][N][K]
// widx: 0 wxi 1 whi 2 wci 3 wxf 4 whf 5 wcf 6 wxg 7 whg 8 wxo 9 who 10 wco 11 wc 12 wi
__device__ __half g_Wt[13ull*WP];

// ---------------- unit tables ----------------
// groups: 0=i 1=f 2=g 3=o 4=resid 5=co 6=c ; each unit = (activation, weight)
__constant__ int c_nunit[7] = {3, 3, 2, 2, 1, 1, 1};
__constant__ unsigned char c_unit_a[7][3] = {
    {0,1,2}, {0,1,2}, {0,1,0}, {0,1,0}, {0,0,0}, {3,0,0}, {4,0,0}
};
__constant__ unsigned char c_unit_w[7][3] = {
    {0,1,2}, {3,4,5}, {6,7,0}, {8,9,0}, {12,0,0}, {10,0,0}, {11,0,0}
};

// ---------------- GEMM tiling ----------------
#define BM 128
#define BN 128
#define BKc 32
#define KPAD 40                    // 32 data + 8 pad: conflict-free ldmatrix
#define THREADS 256
#define A_PL (BM*KPAD)             // 5120 elems
#define W_PL (BN*KPAD)             // 5120 elems
#define ST_ELEMS (A_PL + W_PL)     // 10240 elems = 20480 B / stage
#define STAGES 3
#define SMEM_BYTES (STAGES*ST_ELEMS*2)   // 61440 B -> 2 CTAs/SM

__device__ __forceinline__ uint32_t smem_u32(const void* p) {
    uint32_t a;
    asm("{ .reg .u64 t; cvta.to.shared.u64 t, %1; cvt.u32.u64 %0, t; }" : "=r"(a) : "l"(p));
    return a;
}
__device__ __forceinline__ void cp_async16(uint32_t sdst, const void* gsrc) {
    asm volatile("cp.async.cg.shared.global [%0], [%1], 16;"
                 :: "r"(sdst), "l"(__cvta_generic_to_global(gsrc)) : "memory");
}
#define CP_COMMIT() asm volatile("cp.async.commit_group;" ::: "memory")
#define CP_WAIT1()  asm volatile("cp.async.wait_group 1;" ::: "memory")

__device__ __forceinline__ void ldsm_x4(uint32_t& r0, uint32_t& r1, uint32_t& r2, uint32_t& r3,
                                        uint32_t addr) {
    asm volatile("ldmatrix.sync.aligned.m8n8.x4.shared.b16 {%0,%1,%2,%3}, [%4];"
                 : "=r"(r0), "=r"(r1), "=r"(r2), "=r"(r3) : "r"(addr));
}
__device__ __forceinline__ void mma16816(float* d, const uint32_t* a, uint32_t b0, uint32_t b1) {
    asm volatile(
        "mma.sync.aligned.m16n8k16.row.col.f32.f16.f16.f32 "
        "{%0,%1,%2,%3}, {%4,%5,%6,%7}, {%8,%9}, {%0,%1,%2,%3};"
        : "+f"(d[0]), "+f"(d[1]), "+f"(d[2]), "+f"(d[3])
        : "r"(a[0]), "r"(a[1]), "r"(a[2]), "r"(a[3]), "r"(b0), "r"(b1));
}

// ---------------- single-pass fp16 GEMM ----------------
__global__ void __launch_bounds__(THREADS, 2) gemm_mma(
    int group_base,
    const float* __restrict__ bi, const float* __restrict__ bf_,
    const float* __restrict__ bg, const float* __restrict__ bo)
{
    extern __shared__ __half smem[];
    const uint32_t sb = smem_u32(smem);

    const int tid  = threadIdx.x;
    const int lane = tid & 31;
    const int wid  = tid >> 5;      // 0..7
    const int wm   = wid >> 2;      // 0..1  (64-row slice)
    const int wn   = wid & 3;       // 0..3  (32-col slice)

    const int group = group_base + ((int)blockIdx.y >> 4);
    const int n0    = ((int)blockIdx.y & 15) * BN;
    const int m0    = (int)blockIdx.x * BM;

    const int nunit = c_nunit[group];
    const int nch   = nunit * (Kd / BKc);    // k32 chunks

    // ldmatrix per-lane byte offsets
    const uint32_t a_off = ((uint32_t)(wm*64 + (lane & 15)) * KPAD + ((lane >> 4) << 3)) * 2;
    const uint32_t w_off = ((uint32_t)(wn*32 + (lane & 7) + ((lane >> 4) << 3)) * KPAD
                            + (((lane >> 3) & 1) << 3)) * 2;

    float acc[4][4][4];
    #pragma unroll
    for (int mi = 0; mi < 4; ++mi)
        #pragma unroll
        for (int nj = 0; nj < 4; ++nj)
            #pragma unroll
            for (int r = 0; r < 4; ++r) acc[mi][nj][r] = 0.0f;

    // stage fill: 1024 x 16B data chunks (4 per 80B row; pad left unwritten), 4/thread
    // [0,512): A plane; [512,1024): W plane
    #define ISSUE(tt, buf) do {                                                        \
        const int _t = (tt);                                                           \
        const int _u  = _t >> 6;                                                       \
        const int _kk = (_t & 63) * BKc;                                               \
        const __half* _gA = g_Act + (size_t)c_unit_a[group][_u]*AP;                    \
        const __half* _gW = g_Wt  + (size_t)c_unit_w[group][_u]*WP;                    \
        const uint32_t _sbase = sb + (uint32_t)(buf)*ST_ELEMS*2;                       \
        _Pragma("unroll")                                                              \
        for (int _i = 0; _i < 4; ++_i) {                                               \
            const int _cid = tid + _i*THREADS;                                         \
            if (_cid < 512) {                                                          \
                const int _r = _cid >> 2, _cc = _cid & 3;                              \
                cp_async16(_sbase + (uint32_t)(_r*KPAD + _cc*8)*2,                     \
                           _gA + (size_t)(m0 + _r)*Kd + _kk + _cc*8);                  \
            } else {                                                                   \
                const int _b = _cid - 512;                                             \
                const int _r = _b >> 2, _cc = _b & 3;                                  \
                cp_async16(_sbase + (uint32_t)(A_PL + _r*KPAD + _cc*8)*2,              \
                           _gW + (size_t)(n0 + _r)*Kd + _kk + _cc*8);                  \
            }                                                                          \
        }                                                                              \
    } while (0)

    // prologue: stages 0,1
    ISSUE(0, 0); CP_COMMIT();
    ISSUE(1, 1); CP_COMMIT();

    int buf = 0;
    for (int t = 0; t < nch; ++t) {
        CP_WAIT1();
        __syncthreads();

        if (t + 2 < nch) {
            int nb = buf + 2; if (nb >= 3) nb -= 3;
            ISSUE(t + 2, nb);
        }
        CP_COMMIT();   // always commit to keep group counts aligned

        const uint32_t st  = sb + (uint32_t)buf*ST_ELEMS*2;
        const uint32_t stw = st + (uint32_t)A_PL*2;

        #pragma unroll
        for (int ks = 0; ks < 2; ++ks) {
            const uint32_t kso = (uint32_t)(ks*16)*2;
            uint32_t a[4][4], bw[2][4];
            #pragma unroll
            for (int mi = 0; mi < 4; ++mi)
                ldsm_x4(a[mi][0], a[mi][1], a[mi][2], a[mi][3],
                        st + a_off + (uint32_t)(mi*16*KPAD)*2 + kso);
            #pragma unroll
            for (int nt = 0; nt < 2; ++nt)
                ldsm_x4(bw[nt][0], bw[nt][1], bw[nt][2], bw[nt][3],
                        stw + w_off + (uint32_t)(nt*16*KPAD)*2 + kso);

            #pragma unroll
            for (int mi = 0; mi < 4; ++mi)
                #pragma unroll
                for (int nj = 0; nj < 4; ++nj)
                    mma16816(acc[mi][nj], a[mi],
                             bw[nj >> 1][(nj & 1)*2], bw[nj >> 1][(nj & 1)*2 + 1]);
        }
        if (++buf == 3) buf = 0;
    }

    // ---- epilogue ----
    float* zout; size_t ldz; int colbase;
    const float* bias = nullptr;
    if (group < 5) {
        zout = g_Z;  ldz = 5*Hd; colbase = group*Hd + n0;
        if      (group == 0) bias = bi;
        else if (group == 1) bias = bf_;
        else if (group == 2) bias = bg;
        else if (group == 3) bias = bo;
    } else {
        zout = g_Z2; ldz = 2*Hd; colbase = (group - 5)*Hd + n0;
    }

    const int gid = lane >> 2;
    const int tig = lane & 3;

    #pragma unroll
    for (int mi = 0; mi < 4; ++mi) {
        const int row = m0 + wm*64 + mi*16 + gid;
        #pragma unroll
        for (int nj = 0; nj < 4; ++nj) {
            const int ncol = wn*32 + nj*8 + tig*2;
            float b0 = 0.f, b1 = 0.f;
            if (bias) { b0 = bias[n0 + ncol]; b1 = bias[n0 + ncol + 1]; }
            float2 v0 = make_float2(acc[mi][nj][0] + b0, acc[mi][nj][1] + b1);
            float2 v1 = make_float2(acc[mi][nj][2] + b0, acc[mi][nj][3] + b1);
            *(float2*)(zout + (size_t)row       * ldz + colbase + ncol) = v0;
            *(float2*)(zout + (size_t)(row + 8) * ldz + colbase + ncol) = v1;
        }
    }
}

// ---------------- conversion kernels ----------------
// x/h/c fp32 -> fp16 planes 0..2
__global__ void __launch_bounds__(256) conv_act3(
    const float* __restrict__ x, const float* __restrict__ h, const float* __restrict__ c)
{
    const int act = blockIdx.y;
    const float* s = (act == 0) ? x : (act == 1) ? h : c;
    const size_t i = ((size_t)blockIdx.x*256 + threadIdx.x) * 4;
    float4 v = *(const float4*)(s + i);
    __half* dst = g_Act + (size_t)act*AP;
    dst[i+0] = __float2half_rn(v.x);
    dst[i+1] = __float2half_rn(v.y);
    dst[i+2] = __float2half_rn(v.z);
    dst[i+3] = __float2half_rn(v.w);
}

struct WPtrs { const float* p[13]; };

// W[K][N] fp32 -> g_Wt[N][K] fp16 (transpose via smem tile)
__global__ void __launch_bounds__(256) conv_w(WPtrs wp)
{
    __shared__ float t[32][33];
    const int widx = blockIdx.z;
    const float* w = wp.p[widx];
    const int tx = threadIdx.x & 31;
    const int ty = threadIdx.x >> 5;
    const int k0 = blockIdx.x * 32;
    const int n0 = blockIdx.y * 32;
    #pragma unroll
    for (int r = 0; r < 4; ++r)
        t[ty + 8*r][tx] = w[(size_t)(k0 + ty + 8*r)*Hd + n0 + tx];
    __syncthreads();
    __half* dst = g_Wt + (size_t)widx*WP;
    #pragma unroll
    for (int r = 0; r < 4; ++r) {
        const float v = t[tx][ty + 8*r];
        dst[(size_t)(n0 + ty + 8*r)*Kd + k0 + tx] = __float2half_rn(v);
    }
}

// ---------------- elementwise kernels ----------------
__global__ void __launch_bounds__(256) cell_kernel(
    const float* __restrict__ c_prev, float* __restrict__ c_out)
{
    const int idx = blockIdx.x * 256 + threadIdx.x;
    const int m = idx >> 11;
    const int j = idx & (Hd - 1);
    const float* zr = g_Z + (size_t)m * (5*Hd);
    const float iv = zr[j];
    const float fv = zr[Hd + j];
    const float gv = zr[2*Hd + j];
    const float cp = c_prev[idx];
    const float si = 1.0f / (1.0f + expf(-iv));
    const float sf = 1.0f / (1.0f + expf(-fv));
    const float cn = sf * cp + si * tanhf(gv);
    c_out[idx] = cn;
    const float tc = tanhf(cn);
    g_Act[3*AP + idx] = __float2half_rn(cn);
    g_Act[4*AP + idx] = __float2half_rn(tc);
}

__global__ void __launch_bounds__(256) out_kernel(float* __restrict__ h_out)
{
    const int idx = blockIdx.x * 256 + threadIdx.x;
    const int m = idx >> 11;
    const int j = idx & (Hd - 1);
    const float* zr  = g_Z  + (size_t)m * (5*Hd);
    const float* z2r = g_Z2 + (size_t)m * (2*Hd);
    const float o = zr[3*Hd + j] + z2r[j];
    const float t = z2r[Hd + j] + zr[4*Hd + j];
    h_out[idx] = tanhf(o) * t;
}

// ---------------- host launcher ----------------
extern "C" void kernel_launch(void* const* d_in, const int* in_sizes, int n_in,
                              void* d_out, int out_size)
{
    const float* x      = (const float*)d_in[0];
    const float* h_prev = (const float*)d_in[1];
    const float* c_prev = (const float*)d_in[2];
    const float* w_xi = (const float*)d_in[3];
    const float* w_hi = (const float*)d_in[4];
    const float* w_ci = (const float*)d_in[5];
    const float* w_xf = (const float*)d_in[6];
    const float* w_hf = (const float*)d_in[7];
    const float* w_cf = (const float*)d_in[8];
    const float* w_xg = (const float*)d_in[9];
    const float* w_hg = (const float*)d_in[10];
    const float* w_xo = (const float*)d_in[11];
    const float* w_ho = (const float*)d_in[12];
    const float* w_co = (const float*)d_in[13];
    const float* w_c  = (const float*)d_in[14];
    const float* w_i  = (const float*)d_in[15];
    const float* b_i  = (const float*)d_in[16];
    const float* b_f  = (const float*)d_in[17];
    const float* b_g  = (const float*)d_in[18];
    const float* b_o  = (const float*)d_in[19];

    float* out   = (float*)d_out;
    float* h_out = out;
    float* c_out = out + (size_t)Bsz * Hd;

    cudaFuncSetAttribute(gemm_mma, cudaFuncAttributeMaxDynamicSharedMemorySize, SMEM_BYTES);

    const int n = Bsz * Hd;

    conv_act3<<<dim3(n/(256*4), 3), 256>>>(x, h_prev, c_prev);

    WPtrs wp = {{w_xi, w_hi, w_ci, w_xf, w_hf, w_cf, w_xg, w_hg, w_xo, w_ho, w_co, w_c, w_i}};
    conv_w<<<dim3(Kd/32, Hd/32, 13), 256>>>(wp);

    // gemm1: groups 0..4; 16 n-tiles per group, 32 m-tiles
    gemm_mma<<<dim3(Bsz/BM, 5*16), THREADS, SMEM_BYTES>>>(0, b_i, b_f, b_g, b_o);

    cell_kernel<<<n/256, 256>>>(c_prev, c_out);

    // gemm2: groups 5..6
    gemm_mma<<<dim3(Bsz/BM, 2*16), THREADS, SMEM_BYTES>>>(5, nullptr, nullptr, nullptr, nullptr);

    out_kernel<<<n/256, 256>>>(h_out);
}